// round 12
// baseline (speedup 1.0000x reference)
#include <cuda_runtime.h>
#include <cuda_bf16.h>

// MaxBlurPooling1D: x (16, 8192, 256) f32 -> z (16, 4096, 256) f32
// z[b,j,c] = w0*m[2j-1] + w1*m[2j] + w2*m[2j+1] + w3*m[2j+2]
//   m[l] = max(x[l], x[l+1]) for l<=L-2 ; m[L-1] = x[L-1] ; m[-1] = m[L] = 0
//
// Round-11: R4 kernel byte-identical (best measured: regs 54, 73.7% DRAM,
// 30.5us). Single change, launch-side only: 30KB dynamic smem per block
// caps residency at 7 blocks/SM -> 1036 concurrent -> 2048 blocks = 1.977
// waves (final wave 97.7% full) instead of 1.54 waves (54% tail).
// Wave packing was the one unaddressed inefficiency; codegen untouched.

#define L_DIM  8192
#define C4     64      // 256 f32 channels = 64 float4 lanes
#define J_OUT  4096
#define JPT    16      // outputs per thread along L
#define BY     2       // thread.y chunks per block

#define SMEM_PAD 30720 // occupancy cap: 7 blocks/SM

__device__ __forceinline__ float4 f4max(float4 a, float4 b) {
    return make_float4(fmaxf(a.x, b.x), fmaxf(a.y, b.y),
                       fmaxf(a.z, b.z), fmaxf(a.w, b.w));
}

__global__ void __launch_bounds__(128)
mbp1d_kernel(const float4* __restrict__ x,
             const float*  __restrict__ blur,
             const float*  __restrict__ avg,
             float4* __restrict__ z)
{
    extern __shared__ char smem_pad[];   // unused; occupancy shaping only
    // Prevent any possibility of the pad being optimized out of the launch
    // config path (dynamic smem is honored regardless; this is belt+braces
    // and can never execute: blur is a normalized kernel, sum = 1).
    if (blur[0] == 1234567.0f) smem_pad[threadIdx.x] = 1;

    // Fold blur (b0,b1,b2) and avg (a0,a1) into 4 taps over m[]
    const float b0 = blur[0], b1 = blur[1], b2 = blur[2];
    const float a0 = avg[0],  a1 = avg[1];
    const float w0 = a0 * b0;
    const float w1 = a0 * b1 + a1 * b0;
    const float w2 = a0 * b2 + a1 * b1;
    const float w3 = a1 * b2;

    const int c  = threadIdx.x;                                   // 0..63 float4 lane
    const int b  = blockIdx.y;                                    // batch
    const int j0 = (blockIdx.x * BY + threadIdx.y) * JPT;         // first output row

    const float4* xb = x + (size_t)b * L_DIM * C4 + c;
    float4*       zb = z + ((size_t)b * J_OUT + j0) * C4 + c;

    const float4 zero = make_float4(0.f, 0.f, 0.f, 0.f);

    // Rolling state at loop top for iteration j:
    //   mA = m[2j-1], mB = m[2j], xlast = x[2j+1]
    float4 mA, mB, xlast;
    {
        const float4 x0 = xb[(size_t)(2 * j0) * C4];
        const float4 x1 = xb[(size_t)(2 * j0 + 1) * C4];
        if (j0 == 0) {
            mA = zero;                                            // m[-1] = 0 (pad)
        } else {
            const float4 xm1 = xb[(size_t)(2 * j0 - 1) * C4];
            mA = f4max(xm1, x0);
        }
        mB = f4max(x0, x1);
        xlast = x1;
    }

    #pragma unroll
    for (int t = 0; t < JPT; ++t) {
        const int j  = j0 + t;
        const int r2 = 2 * j + 2;                                 // next even row
        float4 mC, mD;
        if (r2 < L_DIM) {
            const float4 x2 = xb[(size_t)r2 * C4];
            const float4 x3 = xb[(size_t)(r2 + 1) * C4];          // r2 even => r2+1 <= 8191
            mC = f4max(xlast, x2);                                // m[2j+1]
            mD = f4max(x2, x3);                                   // m[2j+2]
            xlast = x3;
        } else {
            // j = 4095: m[8191] = x[8191] (pad is NEG_INF), m[8192] = 0 (zero pad)
            mC = xlast;
            mD = zero;
        }

        float4 o;
        o.x = w0 * mA.x + w1 * mB.x + w2 * mC.x + w3 * mD.x;
        o.y = w0 * mA.y + w1 * mB.y + w2 * mC.y + w3 * mD.y;
        o.z = w0 * mA.z + w1 * mB.z + w2 * mC.z + w3 * mD.z;
        o.w = w0 * mA.w + w1 * mB.w + w2 * mC.w + w3 * mD.w;
        zb[(size_t)t * C4] = o;

        mA = mC;
        mB = mD;
    }
}

extern "C" void kernel_launch(void* const* d_in, const int* in_sizes, int n_in,
                              void* d_out, int out_size)
{
    const float4* x    = (const float4*)d_in[0];   // (16, 8192, 256) f32
    const float*  blur = (const float*)d_in[1];    // (3,1,1)
    const float*  avg  = (const float*)d_in[2];    // (2,1,1)
    float4*       z    = (float4*)d_out;           // (16, 4096, 256) f32

    (void)in_sizes; (void)n_in; (void)out_size;

    dim3 block(C4, BY);                            // (64, 2) = 128 threads
    dim3 grid(J_OUT / (BY * JPT), 16);             // (128, 16) = 2048 blocks
    mbp1d_kernel<<<grid, block, SMEM_PAD>>>(x, blur, avg, z);
}

// round 13
// speedup vs baseline: 1.2474x; 1.2474x over previous
#include <cuda_runtime.h>
#include <cuda_bf16.h>
#include <cstdint>

// MaxBlurPooling1D: x (16, 8192, 256) f32 -> z (16, 4096, 256) f32
// z[b,j,c] = w0*m[2j-1] + w1*m[2j] + w2*m[2j+1] + w3*m[2j+2]
//   m[l] = max(x[l], x[l+1]) for l<=L-2 ; m[L-1] = x[L-1] ; m[-1] = m[L] = 0
//
// Round-12: TMA bulk pipeline. Rows are contiguous 1KB lines, so a chunk's
// whole input footprint (<=35 rows) is ONE contiguous region -> single
// cp.async.bulk per block into SMEM, compute from SMEM. Removes the
// per-warp LDG-slot cap and the ptxas load-schedule lottery (R1..R11: every
// LDG variant plateaus at 5.6-5.9 TB/s, regs-lottery-dependent). TMA writes
// SMEM directly, so losing L1 carveout to smem is harmless (unlike R11).
// 4096 one-chunk blocks -> fine drain granularity; 6 blocks/SM stagger
// load/compute phases to keep DRAM fed.

#define L_DIM  8192
#define CF     256                 // f32 channels per row
#define C4     64                  // float4 lanes per row
#define J_OUT  4096
#define JPT    16                  // output rows per block
#define ROWB   1024                // bytes per input row
#define TILE_ROWS 35               // max rows per chunk footprint
#define SMEM_BYTES (128 + TILE_ROWS * ROWB)

__device__ __forceinline__ float4 f4max(float4 a, float4 b) {
    return make_float4(fmaxf(a.x, b.x), fmaxf(a.y, b.y),
                       fmaxf(a.z, b.z), fmaxf(a.w, b.w));
}

__global__ void __launch_bounds__(128)
mbp1d_tma_kernel(const float* __restrict__ x,
                 const float* __restrict__ blur,
                 const float* __restrict__ avg,
                 float4*      __restrict__ z)
{
    extern __shared__ __align__(128) char smem[];
    uint64_t* mbar = (uint64_t*)smem;                 // [0:8)
    float4*   tile = (float4*)(smem + 128);           // [128: 128+35KB)

    const int c   = threadIdx.x;                      // 0..63 float4 lane
    const int ty  = threadIdx.y;                      // 0..1
    const int tid = ty * 64 + c;
    const int b   = blockIdx.y;                       // batch
    const int j0  = blockIdx.x * JPT;                 // first output row of chunk

    // Input footprint: rows [start, end) of batch b.
    const int start  = (j0 == 0) ? 0 : (2 * j0 - 1);
    const int end    = min(L_DIM, 2 * j0 + 34);
    const int nbytes = (end - start) * ROWB;

    const uint32_t mbar_u32 = (uint32_t)__cvta_generic_to_shared(mbar);
    const uint32_t tile_u32 = (uint32_t)__cvta_generic_to_shared(tile);

    if (tid == 0) {
        asm volatile("mbarrier.init.shared.b64 [%0], 1;" :: "r"(mbar_u32));
    }
    __syncthreads();

    if (tid == 0) {
        asm volatile("mbarrier.arrive.expect_tx.shared.b64 _, [%0], %1;"
                     :: "r"(mbar_u32), "r"((uint32_t)nbytes) : "memory");
        const char* src = (const char*)(x + (size_t)b * L_DIM * CF)
                        + (size_t)start * ROWB;
        asm volatile("cp.async.bulk.shared::cta.global.mbarrier::complete_tx::bytes "
                     "[%0], [%1], %2, [%3];"
                     :: "r"(tile_u32), "l"(src), "r"((uint32_t)nbytes),
                        "r"(mbar_u32) : "memory");
    }

    // Wait for the bulk copy (parity 0; single use).
    {
        uint32_t ready = 0;
        while (!ready) {
            asm volatile(
                "{\n\t.reg .pred p;\n\t"
                "mbarrier.try_wait.parity.acquire.cta.shared::cta.b64 p, [%1], 0, 0x989680;\n\t"
                "selp.b32 %0, 1, 0, p;\n\t}"
                : "=r"(ready) : "r"(mbar_u32) : "memory");
        }
    }

    // Weights: fold blur (3-tap) and avg (2-tap) into 4 taps over m[].
    const float b0 = blur[0], b1 = blur[1], b2 = blur[2];
    const float a0 = avg[0],  a1 = avg[1];
    const float w0 = a0 * b0;
    const float w1 = a0 * b1 + a1 * b0;
    const float w2 = a0 * b2 + a1 * b1;
    const float w3 = a1 * b2;

    // Compute from SMEM. ty splits the chunk: 8 outputs each.
    const float4* S  = tile + c;                      // row stride C4
    const int     js = j0 + 8 * ty;                   // first output for this thread
    float4*       zb = z + ((size_t)b * J_OUT + js) * C4 + c;

    const float4 zero = make_float4(0.f, 0.f, 0.f, 0.f);

    // Rolling state: mA = m[2j-1], mB = m[2j], xlast = x[2j+1]
    float4 mA, mB, xlast;
    {
        const float4 x0 = S[(2 * js - start) * C4];
        const float4 x1 = S[(2 * js + 1 - start) * C4];
        mA = (js == 0) ? zero : f4max(S[(2 * js - 1 - start) * C4], x0);
        mB = f4max(x0, x1);
        xlast = x1;
    }

    #pragma unroll
    for (int t = 0; t < 8; ++t) {
        const int j  = js + t;
        const int r2 = 2 * j + 2;
        float4 mC, mD;
        if (r2 < L_DIM) {
            const float4 x2 = S[(r2 - start) * C4];
            const float4 x3 = S[(r2 + 1 - start) * C4];
            mC = f4max(xlast, x2);                    // m[2j+1]
            mD = f4max(x2, x3);                       // m[2j+2]
            xlast = x3;
        } else {
            // j = 4095: m[8191] = x[8191] (NEG_INF pad), m[8192] = 0 (zero pad)
            mC = xlast;
            mD = zero;
        }

        float4 o;
        o.x = w0 * mA.x + w1 * mB.x + w2 * mC.x + w3 * mD.x;
        o.y = w0 * mA.y + w1 * mB.y + w2 * mC.y + w3 * mD.y;
        o.z = w0 * mA.z + w1 * mB.z + w2 * mC.z + w3 * mD.z;
        o.w = w0 * mA.w + w1 * mB.w + w2 * mC.w + w3 * mD.w;
        zb[(size_t)t * C4] = o;

        mA = mC;
        mB = mD;
    }
}

extern "C" void kernel_launch(void* const* d_in, const int* in_sizes, int n_in,
                              void* d_out, int out_size)
{
    const float* x    = (const float*)d_in[0];     // (16, 8192, 256) f32
    const float* blur = (const float*)d_in[1];     // (3,1,1)
    const float* avg  = (const float*)d_in[2];     // (2,1,1)
    float4*      z    = (float4*)d_out;            // (16, 4096, 256) f32

    (void)in_sizes; (void)n_in; (void)out_size;

    dim3 block(C4, 2);                             // (64, 2) = 128 threads
    dim3 grid(J_OUT / JPT, 16);                    // (256, 16) = 4096 blocks
    mbp1d_tma_kernel<<<grid, block, SMEM_BYTES>>>(x, blur, avg, z);
}